// round 5
// baseline (speedup 1.0000x reference)
#include <cuda_runtime.h>
#include <math.h>

// ---------------------------------------------------------------------------
// SLAMv2: 14-layer MoE-attention transformer, segmented schedule.
// Round 4: TF32 mma.sync GEMM with distance-2 register prefetch pipeline
// (hides ~600cyc global latency that stalled R3 at issue=32%).
// ---------------------------------------------------------------------------

namespace {
constexpr int B = 2, S = 1024, D = 1000, E = 20, HD = 50, TH = 3 * HD;
constexpr int HD_P = 52;  // padded head dim (16B-aligned rows)
constexpr int F = 2048, CYCLES = 3;

constexpr long long NX = (long long)B * S * D;  // 2,048,000
constexpr long long OFF_X    = 0;
constexpr long long OFF_XNEW = OFF_X + NX;
constexpr long long OFF_T    = OFF_XNEW + NX;
constexpr long long OFF_X1   = OFF_T + NX;
constexpr long long OFF_Y    = OFF_X1 + NX;
constexpr long long OFF_A    = OFF_Y + NX;
constexpr long long OFF_ROUT = OFF_A + NX;                       // B*S*E
constexpr long long OFF_H    = OFF_ROUT + (long long)B * S * E;  // B*S*F
constexpr long long OFF_QKV  = OFF_H + (long long)B * S * F;     // B*E*3*S*HD_P
constexpr long long OFF_SC   = OFF_QKV + (long long)B * E * 3 * S * HD_P;
constexpr long long TOTAL    = OFF_SC + (long long)B * E * S * S;

// Segment schedule for S=1024: (0,460) (256,665) (460,870) (665,1024)+wrap 51
constexpr int SEG_ST[4] = {0, 256, 460, 665};
constexpr int SEG_N[4]  = {460, 409, 410, 410};
constexpr int SEG_P1[4] = {460, 409, 410, 359};
}  // namespace

__device__ float g_scratch[TOTAL];

struct GemmP {
  const float* A; const float* Bm; const float* bias; float* C;
  int M, N, K, lda, ldb, ldc;
  int aDiv; long long as1, as2;
  int bDiv; long long bs1, bs2;
  int cDiv; long long cs1, cs2;
  int biasDiv; long long biasS;
  long long splitStride;
  float scale;
  const float* rout; int routN;
};

__device__ __forceinline__ float to_tf32(float x) {
  asm("cvt.rna.tf32.f32 %0, %0;" : "+f"(x));
  return x;
}

// ---------------------------------------------------------------------------
// TF32 tensor-core GEMM, distance-2 register prefetch + 2-stage smem ring.
// BTRANS: 0 -> B is [K,N]; 1 -> B is [N,K] (C = A*B^T).
// EPI: 0 +bias; 1 +bias,GELU; 2 *scale; 3 *routing; 4 +bias,split-QKV store.
// smem layout: X[row][perm(k)], perm(k) = (k&3)*2 + ((k>>2)&1) + (k>>3)*8
// -> fragment (k, k+4) pairs adjacent; one LDS.64 per two mma regs.
// ---------------------------------------------------------------------------
template <int BM, int BN, int WM, int WN, int BTRANS, int EPI, int BALIGN = 1>
__global__ __launch_bounds__(256) void tmma_k(GemmP p) {
  constexpr int BK = 16;
  constexpr int LDS_ = BK + 2;  // 18
  constexpr int NWN = BN / WN;
  constexpr int MT = WM / 16, NT = WN / 8;
  constexpr int AVEC = BM / 64;  // float4 A loads per thread per stage
  constexpr int BVEC = BN / 64;
  static_assert((BM / WM) * (BN / WN) == 8, "need 8 warps");

  __shared__ __align__(16) float As[2][BM][LDS_];
  __shared__ __align__(16) float Bs[2][BN][LDS_];

  const int z = blockIdx.z;
  const float* Ab =
      p.A + (long long)(z / p.aDiv) * p.as1 + (long long)(z % p.aDiv) * p.as2;
  const float* Bb =
      p.Bm + (long long)(z / p.bDiv) * p.bs1 + (long long)(z % p.bDiv) * p.bs2;
  float* Cb =
      p.C + (long long)(z / p.cDiv) * p.cs1 + (long long)(z % p.cDiv) * p.cs2;

  const int m0 = blockIdx.y * BM, n0 = blockIdx.x * BN;
  const int tid = threadIdx.x;
  const int warp = tid >> 5, lane = tid & 31;
  const int g = lane >> 2, t = lane & 3;
  const int wm = (warp / NWN) * WM, wn = (warp % NWN) * WN;

  float4 ar[2][AVEC];  // two staging banks: data j lives in bank j&1
  float4 br[2][BVEC];

  auto ldA = [&](int k0, int bk) {
#pragma unroll
    for (int v = 0; v < AVEC; v++) {
      int idx = tid + v * 256;
      int m = idx >> 2, k4 = (idx & 3) * 4;
      int gm = m0 + m, gk = k0 + k4;
      float4 r = {0.f, 0.f, 0.f, 0.f};
      if (gm < p.M) {
        const float* s = Ab + (long long)gm * p.lda + gk;
        if (gk + 3 < p.K) {
          r = *reinterpret_cast<const float4*>(s);
        } else {
          if (gk < p.K) r.x = s[0];
          if (gk + 1 < p.K) r.y = s[1];
          if (gk + 2 < p.K) r.z = s[2];
        }
      }
      r.x = to_tf32(r.x); r.y = to_tf32(r.y);
      r.z = to_tf32(r.z); r.w = to_tf32(r.w);
      ar[bk][v] = r;
    }
  };
  auto stA = [&](int buf, int bk) {
#pragma unroll
    for (int v = 0; v < AVEC; v++) {
      int idx = tid + v * 256;
      int m = idx >> 2, k4 = (idx & 3) * 4;
      int pos = ((k4 >> 2) & 1) + (k4 >> 3) * 8;
      As[buf][m][pos + 0] = ar[bk][v].x;
      As[buf][m][pos + 2] = ar[bk][v].y;
      As[buf][m][pos + 4] = ar[bk][v].z;
      As[buf][m][pos + 6] = ar[bk][v].w;
    }
  };
  auto ldB = [&](int k0, int bk) {
    if (BTRANS == 0) {
#pragma unroll
      for (int v = 0; v < BVEC; v++) {
        int idx = tid + v * 256;
        int kk = idx / (BN / 4), nn = (idx % (BN / 4)) * 4;
        int gk = k0 + kk, gn = n0 + nn;
        float4 r = {0.f, 0.f, 0.f, 0.f};
        if (gk < p.K) {
          const float* s = Bb + (long long)gk * p.ldb + gn;
          if (BALIGN && gn + 3 < p.N) {
            r = *reinterpret_cast<const float4*>(s);
          } else {
            if (gn < p.N) r.x = s[0];
            if (gn + 1 < p.N) r.y = s[1];
            if (gn + 2 < p.N) r.z = s[2];
            if (gn + 3 < p.N) r.w = s[3];
          }
        }
        r.x = to_tf32(r.x); r.y = to_tf32(r.y);
        r.z = to_tf32(r.z); r.w = to_tf32(r.w);
        br[bk][v] = r;
      }
    } else {
#pragma unroll
      for (int v = 0; v < BVEC; v++) {
        int idx = tid + v * 256;
        int n = idx >> 2, k4 = (idx & 3) * 4;
        int gn = n0 + n, gk = k0 + k4;
        float4 r = {0.f, 0.f, 0.f, 0.f};
        if (gn < p.N) {
          const float* s = Bb + (long long)gn * p.ldb + gk;
          if (gk + 3 < p.K) {
            r = *reinterpret_cast<const float4*>(s);
          } else {
            if (gk < p.K) r.x = s[0];
            if (gk + 1 < p.K) r.y = s[1];
            if (gk + 2 < p.K) r.z = s[2];
          }
        }
        r.x = to_tf32(r.x); r.y = to_tf32(r.y);
        r.z = to_tf32(r.z); r.w = to_tf32(r.w);
        br[bk][v] = r;
      }
    }
  };
  auto stB = [&](int buf, int bk) {
    if (BTRANS == 0) {
#pragma unroll
      for (int v = 0; v < BVEC; v++) {
        int idx = tid + v * 256;
        int kk = idx / (BN / 4), nn = (idx % (BN / 4)) * 4;
        int pos = (kk & 3) * 2 + ((kk >> 2) & 1) + (kk >> 3) * 8;
        Bs[buf][nn + 0][pos] = br[bk][v].x;
        Bs[buf][nn + 1][pos] = br[bk][v].y;
        Bs[buf][nn + 2][pos] = br[bk][v].z;
        Bs[buf][nn + 3][pos] = br[bk][v].w;
      }
    } else {
#pragma unroll
      for (int v = 0; v < BVEC; v++) {
        int idx = tid + v * 256;
        int n = idx >> 2, k4 = (idx & 3) * 4;
        int pos = ((k4 >> 2) & 1) + (k4 >> 3) * 8;
        Bs[buf][n][pos + 0] = br[bk][v].x;
        Bs[buf][n][pos + 2] = br[bk][v].y;
        Bs[buf][n][pos + 4] = br[bk][v].z;
        Bs[buf][n][pos + 6] = br[bk][v].w;
      }
    }
  };

  float c[MT][NT][4];
#pragma unroll
  for (int i = 0; i < MT; i++)
#pragma unroll
    for (int j = 0; j < NT; j++)
#pragma unroll
      for (int r = 0; r < 4; r++) c[i][j][r] = 0.f;

  auto comp = [&](int buf) {
#pragma unroll
    for (int kq = 0; kq < 2; kq++) {
      float2 af[MT][2];
      float2 bf[NT];
#pragma unroll
      for (int mt = 0; mt < MT; mt++) {
        int mrow = wm + mt * 16 + g;
        af[mt][0] =
            *reinterpret_cast<const float2*>(&As[buf][mrow][kq * 8 + 2 * t]);
        af[mt][1] =
            *reinterpret_cast<const float2*>(&As[buf][mrow + 8][kq * 8 + 2 * t]);
      }
#pragma unroll
      for (int nt = 0; nt < NT; nt++)
        bf[nt] = *reinterpret_cast<const float2*>(
            &Bs[buf][wn + nt * 8 + g][kq * 8 + 2 * t]);
#pragma unroll
      for (int mt = 0; mt < MT; mt++)
#pragma unroll
        for (int nt = 0; nt < NT; nt++) {
          asm volatile(
              "mma.sync.aligned.m16n8k8.row.col.f32.tf32.tf32.f32 "
              "{%0,%1,%2,%3}, {%4,%5,%6,%7}, {%8,%9}, {%0,%1,%2,%3};"
              : "+f"(c[mt][nt][0]), "+f"(c[mt][nt][1]), "+f"(c[mt][nt][2]),
                "+f"(c[mt][nt][3])
              : "r"(__float_as_uint(af[mt][0].x)),
                "r"(__float_as_uint(af[mt][1].x)),
                "r"(__float_as_uint(af[mt][0].y)),
                "r"(__float_as_uint(af[mt][1].y)),
                "r"(__float_as_uint(bf[nt].x)), "r"(__float_as_uint(bf[nt].y)));
        }
    }
  };

  // Pipeline: data for iteration j staged in register bank j&1; smem buf j&1.
  // At iter it: issue globals for it+2 (a full iteration of slack before the
  // dependent smem store at iter it+1), compute it, store it+1, sync.
  const int iters = (p.K + BK - 1) / BK;
  ldA(0, 0);
  ldB(0, 0);
  stA(0, 0);
  stB(0, 0);
  if (iters > 1) {
    ldA(BK, 1);
    ldB(BK, 1);
  }
  __syncthreads();
  int buf = 0;
  for (int it = 0; it < iters; it++) {
    if (it + 2 < iters) {
      ldA((it + 2) * BK, it & 1);
      ldB((it + 2) * BK, it & 1);
    }
    comp(buf);
    if (it + 1 < iters) {
      stA(buf ^ 1, (it + 1) & 1);
      stB(buf ^ 1, (it + 1) & 1);
    }
    __syncthreads();
    buf ^= 1;
  }

  const float* biasb = nullptr;
  if ((EPI == 0 || EPI == 1 || EPI == 4) && p.bias)
    biasb = p.bias + (long long)(z % p.biasDiv) * p.biasS;

#pragma unroll
  for (int mt = 0; mt < MT; mt++)
#pragma unroll
    for (int nt = 0; nt < NT; nt++)
#pragma unroll
      for (int r = 0; r < 4; r++) {
        int row = m0 + wm + mt * 16 + g + ((r >> 1) ? 8 : 0);
        int col = n0 + wn + nt * 8 + 2 * t + (r & 1);
        if (row >= p.M || col >= p.N) continue;
        float v = c[mt][nt][r];
        if (biasb) v += biasb[col];
        if (EPI == 1) v = 0.5f * v * (1.f + erff(v * 0.70710678118654752f));
        if (EPI == 2) v *= p.scale;
        if (EPI == 3)
          v *= p.rout[((long long)(z / p.cDiv) * p.routN + row) * E +
                      (z % p.cDiv)];
        if (EPI == 4) {
          int h = col / HD, s2 = col - h * HD;
          Cb[(long long)h * p.splitStride + (long long)row * p.ldc + s2] = v;
        } else {
          Cb[(long long)row * p.ldc + col] = v;
        }
      }
}

// ---------------------------------------------------------------------------
// SIMT SGEMM (tiny routing GEMM, N=20)
// ---------------------------------------------------------------------------
template <int BM, int BN, int BK, int TM, int TN>
__global__ __launch_bounds__((BM / TM) * (BN / TN)) void sgemm2_k(GemmP p) {
  constexpr int NTHR = (BM / TM) * (BN / TN);
  constexpr int TX = BN / TN;
  __shared__ float As[BK][BM + 4];
  __shared__ float Bs[BK][BN + 4];

  const float* Ab = p.A;
  const float* Bb = p.Bm;
  float* Cb = p.C;

  const int m0 = blockIdx.y * BM, n0 = blockIdx.x * BN;
  const int tid = threadIdx.x;
  const int tx = tid % TX, ty = tid / TX;

  float acc[TM][TN];
#pragma unroll
  for (int i = 0; i < TM; i++)
#pragma unroll
    for (int j = 0; j < TN; j++) acc[i][j] = 0.f;

  for (int k0 = 0; k0 < p.K; k0 += BK) {
    for (int idx = tid; idx < BM * BK; idx += NTHR) {
      int m = idx / BK, kk = idx % BK;
      int gm = m0 + m, gk = k0 + kk;
      As[kk][m] = (gm < p.M && gk < p.K) ? Ab[(long long)gm * p.lda + gk] : 0.f;
    }
    for (int idx = tid; idx < BK * BN; idx += NTHR) {
      int kk = idx / BN, nn = idx % BN;
      int gk = k0 + kk, gn = n0 + nn;
      Bs[kk][nn] = (gk < p.K && gn < p.N) ? Bb[(long long)gk * p.ldb + gn] : 0.f;
    }
    __syncthreads();
#pragma unroll
    for (int kk = 0; kk < BK; kk++) {
      float a[TM], b[TN];
#pragma unroll
      for (int i = 0; i < TM; i++) a[i] = As[kk][ty * TM + i];
#pragma unroll
      for (int j = 0; j < TN; j++) b[j] = Bs[kk][tx * TN + j];
#pragma unroll
      for (int i = 0; i < TM; i++)
#pragma unroll
        for (int j = 0; j < TN; j++) acc[i][j] += a[i] * b[j];
    }
    __syncthreads();
  }

#pragma unroll
  for (int i = 0; i < TM; i++) {
    int row = m0 + ty * TM + i;
    if (row >= p.M) continue;
#pragma unroll
    for (int j = 0; j < TN; j++) {
      int col = n0 + tx * TN + j;
      if (col >= p.N) continue;
      float v = acc[i][j] + (p.bias ? p.bias[col] : 0.f);
      Cb[(long long)row * p.ldc + col] = v;
    }
  }
}

// ---------------------------------------------------------------------------
// Small kernels
// ---------------------------------------------------------------------------
__global__ void copy_k(float* dst, const float* src, long long n) {
  long long i = (long long)blockIdx.x * blockDim.x + threadIdx.x;
  if (i < n) dst[i] = src[i];
}

__global__ void zero_k(float* dst, long long n) {
  long long i = (long long)blockIdx.x * blockDim.x + threadIdx.x;
  if (i < n) dst[i] = 0.f;
}

__global__ void gather_k(float* dst, const float* src, int nseg, int st, int p1) {
  long long i = (long long)blockIdx.x * blockDim.x + threadIdx.x;
  long long tot = (long long)B * nseg * D;
  if (i >= tot) return;
  int d = (int)(i % D);
  long long r = i / D;
  int ii = (int)(r % nseg);
  int b_ = (int)(r / nseg);
  int si = (ii < p1) ? (st + ii) : (ii - p1);
  dst[i] = src[((long long)b_ * S + si) * D + d];
}

__global__ void scatter_add_k(float* dst, const float* src, int nseg, int st,
                              int p1) {
  long long i = (long long)blockIdx.x * blockDim.x + threadIdx.x;
  long long tot = (long long)B * nseg * D;
  if (i >= tot) return;
  int d = (int)(i % D);
  long long r = i / D;
  int ii = (int)(r % nseg);
  int b_ = (int)(r / nseg);
  int si = (ii < p1) ? (st + ii) : (ii - p1);
  dst[((long long)b_ * S + si) * D + d] += src[i];
}

__device__ __forceinline__ float seg_cnt(int i) {
  float c = 0.f;
  c += (i < 460);
  c += (i >= 256 && i < 665);
  c += (i >= 460 && i < 870);
  c += (i >= 665);
  c += (i < 51);
  return c;
}

__global__ void div_counts_k(float* x, const float* xn) {
  long long i = (long long)blockIdx.x * blockDim.x + threadIdx.x;
  if (i >= NX) return;
  int ii = (int)((i / D) % S);
  x[i] = xn[i] / seg_cnt(ii);
}

__global__ void softmaxE_k(float* r, int rows) {
  int i = blockIdx.x * blockDim.x + threadIdx.x;
  if (i >= rows) return;
  float* p = r + (long long)i * E;
  float m = -1e30f;
  for (int e = 0; e < E; e++) m = fmaxf(m, p[e]);
  float s = 0.f;
  for (int e = 0; e < E; e++) {
    float v = __expf(p[e] - m);
    p[e] = v;
    s += v;
  }
  float inv = 1.f / s;
  for (int e = 0; e < E; e++) p[e] *= inv;
}

__global__ void softmax_rows_k(float* s, int n, int ld) {
  float* row = s + (long long)blockIdx.y * n * ld + (long long)blockIdx.x * ld;
  __shared__ float red[32];
  __shared__ float bcast;
  int tid = threadIdx.x;
  int nw = blockDim.x >> 5;

  float m = -1e30f;
  for (int j = tid; j < n; j += blockDim.x) m = fmaxf(m, row[j]);
  for (int o = 16; o; o >>= 1) m = fmaxf(m, __shfl_xor_sync(0xffffffffu, m, o));
  if ((tid & 31) == 0) red[tid >> 5] = m;
  __syncthreads();
  if (tid < 32) {
    float v = (tid < nw) ? red[tid] : -1e30f;
    for (int o = 16; o; o >>= 1) v = fmaxf(v, __shfl_xor_sync(0xffffffffu, v, o));
    if (tid == 0) bcast = v;
  }
  __syncthreads();
  m = bcast;

  float sum = 0.f;
  for (int j = tid; j < n; j += blockDim.x) {
    float e = __expf(row[j] - m);
    row[j] = e;
    sum += e;
  }
  for (int o = 16; o; o >>= 1) sum += __shfl_xor_sync(0xffffffffu, sum, o);
  if ((tid & 31) == 0) red[tid >> 5] = sum;
  __syncthreads();
  if (tid < 32) {
    float v = (tid < nw) ? red[tid] : 0.f;
    for (int o = 16; o; o >>= 1) v += __shfl_xor_sync(0xffffffffu, v, o);
    if (tid == 0) bcast = v;
  }
  __syncthreads();
  float inv = 1.f / bcast;
  for (int j = tid; j < n; j += blockDim.x) row[j] *= inv;
}

__global__ void add_ln_k(const float* x, const float* r, const float* g,
                         const float* b, float* out) {
  long long base = (long long)blockIdx.x * D;
  __shared__ float buf[D];
  __shared__ float redA[32], redB[32];
  __shared__ float sh_m, sh_inv;
  int tid = threadIdx.x;
  int nw = blockDim.x >> 5;

  float s = 0.f, s2 = 0.f;
  for (int d = tid; d < D; d += blockDim.x) {
    float v = x[base + d] + r[base + d];
    buf[d] = v;
    s += v;
    s2 += v * v;
  }
  for (int o = 16; o; o >>= 1) {
    s += __shfl_xor_sync(0xffffffffu, s, o);
    s2 += __shfl_xor_sync(0xffffffffu, s2, o);
  }
  if ((tid & 31) == 0) { redA[tid >> 5] = s; redB[tid >> 5] = s2; }
  __syncthreads();
  if (tid < 32) {
    float a2 = (tid < nw) ? redA[tid] : 0.f;
    float b2 = (tid < nw) ? redB[tid] : 0.f;
    for (int o = 16; o; o >>= 1) {
      a2 += __shfl_xor_sync(0xffffffffu, a2, o);
      b2 += __shfl_xor_sync(0xffffffffu, b2, o);
    }
    if (tid == 0) {
      float mean = a2 / D;
      float var = b2 / D - mean * mean;
      sh_m = mean;
      sh_inv = rsqrtf(var + 1e-5f);
    }
  }
  __syncthreads();
  float mean = sh_m, inv = sh_inv;
  for (int d = tid; d < D; d += blockDim.x)
    out[base + d] = (buf[d] - mean) * inv * g[d] + b[d];
}

// ---------------------------------------------------------------------------
// Host-side driver
// ---------------------------------------------------------------------------
static inline int cdiv(int a, int b) { return (a + b - 1) / b; }

struct Wts {
  const float *ew, *eb, *rw, *rb, *ow, *ob, *l1g, *l1b, *w1, *b1, *w2, *b2,
      *l2g, *l2b;
};

static void run_block(float* sc, const float* t, float* out, int layer, int n,
                      const Wts& w) {
  const int M = B * n;
  const int n4 = (n + 3) & ~3;
  float* rout = sc + OFF_ROUT;
  float* qkv = sc + OFF_QKV;
  float* sco = sc + OFF_SC;
  float* y = sc + OFF_Y;
  float* a = sc + OFF_A;
  float* x1 = sc + OFF_X1;
  float* h = sc + OFF_H;

  GemmP p;
  auto reset = [&]() {
    p = GemmP{};
    p.aDiv = p.bDiv = p.cDiv = p.biasDiv = 1;
    p.scale = 1.f;
  };

  // 1. routing logits + softmax over experts (fp32 SIMT, N=20)
  reset();
  p.A = t; p.Bm = w.rw + (long long)layer * D * E;
  p.bias = w.rb + (long long)layer * E; p.C = rout;
  p.M = M; p.N = E; p.K = D; p.lda = D; p.ldb = E; p.ldc = E;
  sgemm2_k<64, 64, 16, 4, 4><<<dim3(1, cdiv(M, 64), 1), 256>>>(p);
  softmaxE_k<<<cdiv(M, 256), 256>>>(rout, M);

  // 2. qkv = t @ expert_w[e] + expert_b[e], split-stored as Q/K/V [z][3][n][52]
  reset();
  p.A = t; p.lda = D; p.aDiv = E; p.as1 = (long long)n * D;
  p.Bm = w.ew + (long long)layer * E * D * TH; p.ldb = TH;
  p.bDiv = E; p.bs2 = (long long)D * TH;
  p.bias = w.eb + (long long)layer * E * TH; p.biasDiv = E; p.biasS = TH;
  p.C = qkv; p.ldc = HD_P; p.cs1 = 3LL * n * HD_P;
  p.splitStride = (long long)n * HD_P;
  p.M = n; p.N = TH; p.K = D;
  tmma_k<128, 64, 32, 32, 0, 4, 0>
      <<<dim3(cdiv(TH, 64), cdiv(n, 128), B * E), 256>>>(p);

  // 3. scores = Q @ K^T * HD^-0.5 (NT), batched over (b,e)
  reset();
  p.A = qkv; p.lda = HD_P; p.as1 = 3LL * n * HD_P;
  p.Bm = qkv + (long long)n * HD_P; p.ldb = HD_P; p.bs1 = 3LL * n * HD_P;
  p.C = sco; p.ldc = n4; p.cs1 = (long long)n * n4;
  p.M = n; p.N = n; p.K = HD;
  p.scale = 0.14142135623730950488f;  // 1/sqrt(50)
  tmma_k<128, 64, 32, 32, 1, 2>
      <<<dim3(cdiv(n, 64), cdiv(n, 128), B * E), 256>>>(p);

  softmax_rows_k<<<dim3(n, B * E), 256>>>(sco, n, n4);

  // 4. y[:, e*HD:(e+1)*HD] = (P @ V) * routing[b, s, e]
  reset();
  p.A = sco; p.lda = n4; p.as1 = (long long)n * n4;
  p.Bm = qkv + 2LL * n * HD_P; p.ldb = HD_P; p.bs1 = 3LL * n * HD_P;
  p.C = y; p.ldc = D; p.cDiv = E; p.cs1 = (long long)n * D; p.cs2 = HD;
  p.M = n; p.N = HD; p.K = n;
  p.rout = rout; p.routN = n;
  tmma_k<128, 64, 32, 32, 0, 3><<<dim3(1, cdiv(n, 128), B * E), 256>>>(p);

  // 5. a = y @ out_w + out_b
  reset();
  p.A = y; p.lda = D;
  p.Bm = w.ow + (long long)layer * D * D; p.ldb = D;
  p.bias = w.ob + (long long)layer * D;
  p.C = a; p.ldc = D;
  p.M = M; p.N = D; p.K = D;
  tmma_k<64, 128, 32, 32, 0, 0>
      <<<dim3(cdiv(D, 128), cdiv(M, 64), 1), 256>>>(p);

  // 6. x1 = LN1(t + a)
  add_ln_k<<<M, 256>>>(t, a, w.l1g + (long long)layer * D,
                       w.l1b + (long long)layer * D, x1);

  // 7. h = gelu(x1 @ ff_w1 + ff_b1)
  reset();
  p.A = x1; p.lda = D;
  p.Bm = w.w1 + (long long)layer * D * F; p.ldb = F;
  p.bias = w.b1 + (long long)layer * F;
  p.C = h; p.ldc = F;
  p.M = M; p.N = F; p.K = D;
  tmma_k<64, 128, 32, 32, 0, 1>
      <<<dim3(cdiv(F, 128), cdiv(M, 64), 1), 256>>>(p);

  // 8. f = h @ ff_w2 + ff_b2 (into y, reuse)
  reset();
  p.A = h; p.lda = F;
  p.Bm = w.w2 + (long long)layer * F * D; p.ldb = D;
  p.bias = w.b2 + (long long)layer * D;
  p.C = y; p.ldc = D;
  p.M = M; p.N = D; p.K = F;
  tmma_k<64, 128, 32, 32, 0, 0>
      <<<dim3(cdiv(D, 128), cdiv(M, 64), 1), 256>>>(p);

  // 9. out = LN2(x1 + f)
  add_ln_k<<<M, 256>>>(x1, y, w.l2g + (long long)layer * D,
                       w.l2b + (long long)layer * D, out);
}

extern "C" void kernel_launch(void* const* d_in, const int* in_sizes, int n_in,
                              void* d_out, int out_size) {
  (void)in_sizes; (void)n_in; (void)out_size;
  float* sc = nullptr;
  cudaGetSymbolAddress((void**)&sc, g_scratch);

  const float* x_in = (const float*)d_in[0];
  Wts w;
  w.ew = (const float*)d_in[1];  w.eb = (const float*)d_in[2];
  w.rw = (const float*)d_in[3];  w.rb = (const float*)d_in[4];
  w.ow = (const float*)d_in[5];  w.ob = (const float*)d_in[6];
  w.l1g = (const float*)d_in[7]; w.l1b = (const float*)d_in[8];
  w.w1 = (const float*)d_in[9];  w.b1 = (const float*)d_in[10];
  w.w2 = (const float*)d_in[11]; w.b2 = (const float*)d_in[12];
  w.l2g = (const float*)d_in[13]; w.l2b = (const float*)d_in[14];

  copy_k<<<cdiv((int)NX, 256), 256>>>(sc + OFF_X, x_in, NX);

  run_block(sc, sc + OFF_X, sc + OFF_X, 0, S, w);

  for (int c = 0; c < CYCLES; c++) {
    zero_k<<<cdiv((int)NX, 256), 256>>>(sc + OFF_XNEW, NX);
    for (int j = 0; j < 4; j++) {
      int nseg = SEG_N[j];
      int tot = B * nseg * D;
      gather_k<<<cdiv(tot, 256), 256>>>(sc + OFF_T, sc + OFF_X, nseg, SEG_ST[j],
                                        SEG_P1[j]);
      run_block(sc, sc + OFF_T, sc + OFF_A, 1 + 4 * c + j, nseg, w);
      scatter_add_k<<<cdiv(tot, 256), 256>>>(sc + OFF_XNEW, sc + OFF_A, nseg,
                                             SEG_ST[j], SEG_P1[j]);
    }
    div_counts_k<<<cdiv((int)NX, 256), 256>>>(sc + OFF_X, sc + OFF_XNEW);
  }

  run_block(sc, sc + OFF_X, (float*)d_out, 13, S, w);
}

// round 6
// speedup vs baseline: 1.0062x; 1.0062x over previous
#include <cuda_runtime.h>
#include <math.h>

// ---------------------------------------------------------------------------
// SLAMv2: 14-layer MoE-attention transformer, segmented schedule.
// Round 4: TF32 mma.sync GEMM with distance-2 register prefetch pipeline
// (hides ~600cyc global latency that stalled R3 at issue=32%).
// ---------------------------------------------------------------------------

namespace {
constexpr int B = 2, S = 1024, D = 1000, E = 20, HD = 50, TH = 3 * HD;
constexpr int HD_P = 52;  // padded head dim (16B-aligned rows)
constexpr int F = 2048, CYCLES = 3;

constexpr long long NX = (long long)B * S * D;  // 2,048,000
constexpr long long OFF_X    = 0;
constexpr long long OFF_XNEW = OFF_X + NX;
constexpr long long OFF_T    = OFF_XNEW + NX;
constexpr long long OFF_X1   = OFF_T + NX;
constexpr long long OFF_Y    = OFF_X1 + NX;
constexpr long long OFF_A    = OFF_Y + NX;
constexpr long long OFF_ROUT = OFF_A + NX;                       // B*S*E
constexpr long long OFF_H    = OFF_ROUT + (long long)B * S * E;  // B*S*F
constexpr long long OFF_QKV  = OFF_H + (long long)B * S * F;     // B*E*3*S*HD_P
constexpr long long OFF_SC   = OFF_QKV + (long long)B * E * 3 * S * HD_P;
constexpr long long TOTAL    = OFF_SC + (long long)B * E * S * S;

// Segment schedule for S=1024: (0,460) (256,665) (460,870) (665,1024)+wrap 51
constexpr int SEG_ST[4] = {0, 256, 460, 665};
constexpr int SEG_N[4]  = {460, 409, 410, 410};
constexpr int SEG_P1[4] = {460, 409, 410, 359};
}  // namespace

__device__ float g_scratch[TOTAL];

struct GemmP {
  const float* A; const float* Bm; const float* bias; float* C;
  int M, N, K, lda, ldb, ldc;
  int aDiv; long long as1, as2;
  int bDiv; long long bs1, bs2;
  int cDiv; long long cs1, cs2;
  int biasDiv; long long biasS;
  long long splitStride;
  float scale;
  const float* rout; int routN;
};

__device__ __forceinline__ float to_tf32(float x) {
  asm("cvt.rna.tf32.f32 %0, %0;" : "+f"(x));
  return x;
}

// ---------------------------------------------------------------------------
// TF32 tensor-core GEMM, distance-2 register prefetch + 2-stage smem ring.
// BTRANS: 0 -> B is [K,N]; 1 -> B is [N,K] (C = A*B^T).
// EPI: 0 +bias; 1 +bias,GELU; 2 *scale; 3 *routing; 4 +bias,split-QKV store.
// smem layout: X[row][perm(k)], perm(k) = (k&3)*2 + ((k>>2)&1) + (k>>3)*8
// -> fragment (k, k+4) pairs adjacent; one LDS.64 per two mma regs.
// ---------------------------------------------------------------------------
template <int BM, int BN, int WM, int WN, int BTRANS, int EPI, int BALIGN = 1>
__global__ __launch_bounds__(256) void tmma_k(GemmP p) {
  constexpr int BK = 16;
  constexpr int LDS_ = BK + 2;  // 18
  constexpr int NWN = BN / WN;
  constexpr int MT = WM / 16, NT = WN / 8;
  constexpr int AVEC = BM / 64;  // float4 A loads per thread per stage
  constexpr int BVEC = BN / 64;
  static_assert((BM / WM) * (BN / WN) == 8, "need 8 warps");

  __shared__ __align__(16) float As[2][BM][LDS_];
  __shared__ __align__(16) float Bs[2][BN][LDS_];

  const int z = blockIdx.z;
  const float* Ab =
      p.A + (long long)(z / p.aDiv) * p.as1 + (long long)(z % p.aDiv) * p.as2;
  const float* Bb =
      p.Bm + (long long)(z / p.bDiv) * p.bs1 + (long long)(z % p.bDiv) * p.bs2;
  float* Cb =
      p.C + (long long)(z / p.cDiv) * p.cs1 + (long long)(z % p.cDiv) * p.cs2;

  const int m0 = blockIdx.y * BM, n0 = blockIdx.x * BN;
  const int tid = threadIdx.x;
  const int warp = tid >> 5, lane = tid & 31;
  const int g = lane >> 2, t = lane & 3;
  const int wm = (warp / NWN) * WM, wn = (warp % NWN) * WN;

  float4 ar[2][AVEC];  // two staging banks: data j lives in bank j&1
  float4 br[2][BVEC];

  auto ldA = [&](int k0, int bk) {
#pragma unroll
    for (int v = 0; v < AVEC; v++) {
      int idx = tid + v * 256;
      int m = idx >> 2, k4 = (idx & 3) * 4;
      int gm = m0 + m, gk = k0 + k4;
      float4 r = {0.f, 0.f, 0.f, 0.f};
      if (gm < p.M) {
        const float* s = Ab + (long long)gm * p.lda + gk;
        if (gk + 3 < p.K) {
          r = *reinterpret_cast<const float4*>(s);
        } else {
          if (gk < p.K) r.x = s[0];
          if (gk + 1 < p.K) r.y = s[1];
          if (gk + 2 < p.K) r.z = s[2];
        }
      }
      r.x = to_tf32(r.x); r.y = to_tf32(r.y);
      r.z = to_tf32(r.z); r.w = to_tf32(r.w);
      ar[bk][v] = r;
    }
  };
  auto stA = [&](int buf, int bk) {
#pragma unroll
    for (int v = 0; v < AVEC; v++) {
      int idx = tid + v * 256;
      int m = idx >> 2, k4 = (idx & 3) * 4;
      int pos = ((k4 >> 2) & 1) + (k4 >> 3) * 8;
      As[buf][m][pos + 0] = ar[bk][v].x;
      As[buf][m][pos + 2] = ar[bk][v].y;
      As[buf][m][pos + 4] = ar[bk][v].z;
      As[buf][m][pos + 6] = ar[bk][v].w;
    }
  };
  auto ldB = [&](int k0, int bk) {
    if (BTRANS == 0) {
#pragma unroll
      for (int v = 0; v < BVEC; v++) {
        int idx = tid + v * 256;
        int kk = idx / (BN / 4), nn = (idx % (BN / 4)) * 4;
        int gk = k0 + kk, gn = n0 + nn;
        float4 r = {0.f, 0.f, 0.f, 0.f};
        if (gk < p.K) {
          const float* s = Bb + (long long)gk * p.ldb + gn;
          if (BALIGN && gn + 3 < p.N) {
            r = *reinterpret_cast<const float4*>(s);
          } else {
            if (gn < p.N) r.x = s[0];
            if (gn + 1 < p.N) r.y = s[1];
            if (gn + 2 < p.N) r.z = s[2];
            if (gn + 3 < p.N) r.w = s[3];
          }
        }
        r.x = to_tf32(r.x); r.y = to_tf32(r.y);
        r.z = to_tf32(r.z); r.w = to_tf32(r.w);
        br[bk][v] = r;
      }
    } else {
#pragma unroll
      for (int v = 0; v < BVEC; v++) {
        int idx = tid + v * 256;
        int n = idx >> 2, k4 = (idx & 3) * 4;
        int gn = n0 + n, gk = k0 + k4;
        float4 r = {0.f, 0.f, 0.f, 0.f};
        if (gn < p.N) {
          const float* s = Bb + (long long)gn * p.ldb + gk;
          if (gk + 3 < p.K) {
            r = *reinterpret_cast<const float4*>(s);
          } else {
            if (gk < p.K) r.x = s[0];
            if (gk + 1 < p.K) r.y = s[1];
            if (gk + 2 < p.K) r.z = s[2];
          }
        }
        r.x = to_tf32(r.x); r.y = to_tf32(r.y);
        r.z = to_tf32(r.z); r.w = to_tf32(r.w);
        br[bk][v] = r;
      }
    }
  };
  auto stB = [&](int buf, int bk) {
    if (BTRANS == 0) {
#pragma unroll
      for (int v = 0; v < BVEC; v++) {
        int idx = tid + v * 256;
        int kk = idx / (BN / 4), nn = (idx % (BN / 4)) * 4;
        int pos = (kk & 3) * 2 + ((kk >> 2) & 1) + (kk >> 3) * 8;
        Bs[buf][nn + 0][pos] = br[bk][v].x;
        Bs[buf][nn + 1][pos] = br[bk][v].y;
        Bs[buf][nn + 2][pos] = br[bk][v].z;
        Bs[buf][nn + 3][pos] = br[bk][v].w;
      }
    } else {
#pragma unroll
      for (int v = 0; v < BVEC; v++) {
        int idx = tid + v * 256;
        int n = idx >> 2, k4 = (idx & 3) * 4;
        int pos = ((k4 >> 2) & 1) + (k4 >> 3) * 8;
        Bs[buf][n][pos + 0] = br[bk][v].x;
        Bs[buf][n][pos + 2] = br[bk][v].y;
        Bs[buf][n][pos + 4] = br[bk][v].z;
        Bs[buf][n][pos + 6] = br[bk][v].w;
      }
    }
  };

  float c[MT][NT][4];
#pragma unroll
  for (int i = 0; i < MT; i++)
#pragma unroll
    for (int j = 0; j < NT; j++)
#pragma unroll
      for (int r = 0; r < 4; r++) c[i][j][r] = 0.f;

  auto comp = [&](int buf) {
#pragma unroll
    for (int kq = 0; kq < 2; kq++) {
      float2 af[MT][2];
      float2 bf[NT];
#pragma unroll
      for (int mt = 0; mt < MT; mt++) {
        int mrow = wm + mt * 16 + g;
        af[mt][0] =
            *reinterpret_cast<const float2*>(&As[buf][mrow][kq * 8 + 2 * t]);
        af[mt][1] =
            *reinterpret_cast<const float2*>(&As[buf][mrow + 8][kq * 8 + 2 * t]);
      }
#pragma unroll
      for (int nt = 0; nt < NT; nt++)
        bf[nt] = *reinterpret_cast<const float2*>(
            &Bs[buf][wn + nt * 8 + g][kq * 8 + 2 * t]);
#pragma unroll
      for (int mt = 0; mt < MT; mt++)
#pragma unroll
        for (int nt = 0; nt < NT; nt++) {
          asm volatile(
              "mma.sync.aligned.m16n8k8.row.col.f32.tf32.tf32.f32 "
              "{%0,%1,%2,%3}, {%4,%5,%6,%7}, {%8,%9}, {%0,%1,%2,%3};"
              : "+f"(c[mt][nt][0]), "+f"(c[mt][nt][1]), "+f"(c[mt][nt][2]),
                "+f"(c[mt][nt][3])
              : "r"(__float_as_uint(af[mt][0].x)),
                "r"(__float_as_uint(af[mt][1].x)),
                "r"(__float_as_uint(af[mt][0].y)),
                "r"(__float_as_uint(af[mt][1].y)),
                "r"(__float_as_uint(bf[nt].x)), "r"(__float_as_uint(bf[nt].y)));
        }
    }
  };

  // Pipeline: data for iteration j staged in register bank j&1; smem buf j&1.
  // At iter it: issue globals for it+2 (a full iteration of slack before the
  // dependent smem store at iter it+1), compute it, store it+1, sync.
  const int iters = (p.K + BK - 1) / BK;
  ldA(0, 0);
  ldB(0, 0);
  stA(0, 0);
  stB(0, 0);
  if (iters > 1) {
    ldA(BK, 1);
    ldB(BK, 1);
  }
  __syncthreads();
  int buf = 0;
  for (int it = 0; it < iters; it++) {
    if (it + 2 < iters) {
      ldA((it + 2) * BK, it & 1);
      ldB((it + 2) * BK, it & 1);
    }
    comp(buf);
    if (it + 1 < iters) {
      stA(buf ^ 1, (it + 1) & 1);
      stB(buf ^ 1, (it + 1) & 1);
    }
    __syncthreads();
    buf ^= 1;
  }

  const float* biasb = nullptr;
  if ((EPI == 0 || EPI == 1 || EPI == 4) && p.bias)
    biasb = p.bias + (long long)(z % p.biasDiv) * p.biasS;

#pragma unroll
  for (int mt = 0; mt < MT; mt++)
#pragma unroll
    for (int nt = 0; nt < NT; nt++)
#pragma unroll
      for (int r = 0; r < 4; r++) {
        int row = m0 + wm + mt * 16 + g + ((r >> 1) ? 8 : 0);
        int col = n0 + wn + nt * 8 + 2 * t + (r & 1);
        if (row >= p.M || col >= p.N) continue;
        float v = c[mt][nt][r];
        if (biasb) v += biasb[col];
        if (EPI == 1) v = 0.5f * v * (1.f + erff(v * 0.70710678118654752f));
        if (EPI == 2) v *= p.scale;
        if (EPI == 3)
          v *= p.rout[((long long)(z / p.cDiv) * p.routN + row) * E +
                      (z % p.cDiv)];
        if (EPI == 4) {
          int h = col / HD, s2 = col - h * HD;
          Cb[(long long)h * p.splitStride + (long long)row * p.ldc + s2] = v;
        } else {
          Cb[(long long)row * p.ldc + col] = v;
        }
      }
}

// ---------------------------------------------------------------------------
// SIMT SGEMM (tiny routing GEMM, N=20)
// ---------------------------------------------------------------------------
template <int BM, int BN, int BK, int TM, int TN>
__global__ __launch_bounds__((BM / TM) * (BN / TN)) void sgemm2_k(GemmP p) {
  constexpr int NTHR = (BM / TM) * (BN / TN);
  constexpr int TX = BN / TN;
  __shared__ float As[BK][BM + 4];
  __shared__ float Bs[BK][BN + 4];

  const float* Ab = p.A;
  const float* Bb = p.Bm;
  float* Cb = p.C;

  const int m0 = blockIdx.y * BM, n0 = blockIdx.x * BN;
  const int tid = threadIdx.x;
  const int tx = tid % TX, ty = tid / TX;

  float acc[TM][TN];
#pragma unroll
  for (int i = 0; i < TM; i++)
#pragma unroll
    for (int j = 0; j < TN; j++) acc[i][j] = 0.f;

  for (int k0 = 0; k0 < p.K; k0 += BK) {
    for (int idx = tid; idx < BM * BK; idx += NTHR) {
      int m = idx / BK, kk = idx % BK;
      int gm = m0 + m, gk = k0 + kk;
      As[kk][m] = (gm < p.M && gk < p.K) ? Ab[(long long)gm * p.lda + gk] : 0.f;
    }
    for (int idx = tid; idx < BK * BN; idx += NTHR) {
      int kk = idx / BN, nn = idx % BN;
      int gk = k0 + kk, gn = n0 + nn;
      Bs[kk][nn] = (gk < p.K && gn < p.N) ? Bb[(long long)gk * p.ldb + gn] : 0.f;
    }
    __syncthreads();
#pragma unroll
    for (int kk = 0; kk < BK; kk++) {
      float a[TM], b[TN];
#pragma unroll
      for (int i = 0; i < TM; i++) a[i] = As[kk][ty * TM + i];
#pragma unroll
      for (int j = 0; j < TN; j++) b[j] = Bs[kk][tx * TN + j];
#pragma unroll
      for (int i = 0; i < TM; i++)
#pragma unroll
        for (int j = 0; j < TN; j++) acc[i][j] += a[i] * b[j];
    }
    __syncthreads();
  }

#pragma unroll
  for (int i = 0; i < TM; i++) {
    int row = m0 + ty * TM + i;
    if (row >= p.M) continue;
#pragma unroll
    for (int j = 0; j < TN; j++) {
      int col = n0 + tx * TN + j;
      if (col >= p.N) continue;
      float v = acc[i][j] + (p.bias ? p.bias[col] : 0.f);
      Cb[(long long)row * p.ldc + col] = v;
    }
  }
}

// ---------------------------------------------------------------------------
// Small kernels
// ---------------------------------------------------------------------------
__global__ void copy_k(float* dst, const float* src, long long n) {
  long long i = (long long)blockIdx.x * blockDim.x + threadIdx.x;
  if (i < n) dst[i] = src[i];
}

__global__ void zero_k(float* dst, long long n) {
  long long i = (long long)blockIdx.x * blockDim.x + threadIdx.x;
  if (i < n) dst[i] = 0.f;
}

__global__ void gather_k(float* dst, const float* src, int nseg, int st, int p1) {
  long long i = (long long)blockIdx.x * blockDim.x + threadIdx.x;
  long long tot = (long long)B * nseg * D;
  if (i >= tot) return;
  int d = (int)(i % D);
  long long r = i / D;
  int ii = (int)(r % nseg);
  int b_ = (int)(r / nseg);
  int si = (ii < p1) ? (st + ii) : (ii - p1);
  dst[i] = src[((long long)b_ * S + si) * D + d];
}

__global__ void scatter_add_k(float* dst, const float* src, int nseg, int st,
                              int p1) {
  long long i = (long long)blockIdx.x * blockDim.x + threadIdx.x;
  long long tot = (long long)B * nseg * D;
  if (i >= tot) return;
  int d = (int)(i % D);
  long long r = i / D;
  int ii = (int)(r % nseg);
  int b_ = (int)(r / nseg);
  int si = (ii < p1) ? (st + ii) : (ii - p1);
  dst[((long long)b_ * S + si) * D + d] += src[i];
}

__device__ __forceinline__ float seg_cnt(int i) {
  float c = 0.f;
  c += (i < 460);
  c += (i >= 256 && i < 665);
  c += (i >= 460 && i < 870);
  c += (i >= 665);
  c += (i < 51);
  return c;
}

__global__ void div_counts_k(float* x, const float* xn) {
  long long i = (long long)blockIdx.x * blockDim.x + threadIdx.x;
  if (i >= NX) return;
  int ii = (int)((i / D) % S);
  x[i] = xn[i] / seg_cnt(ii);
}

__global__ void softmaxE_k(float* r, int rows) {
  int i = blockIdx.x * blockDim.x + threadIdx.x;
  if (i >= rows) return;
  float* p = r + (long long)i * E;
  float m = -1e30f;
  for (int e = 0; e < E; e++) m = fmaxf(m, p[e]);
  float s = 0.f;
  for (int e = 0; e < E; e++) {
    float v = __expf(p[e] - m);
    p[e] = v;
    s += v;
  }
  float inv = 1.f / s;
  for (int e = 0; e < E; e++) p[e] *= inv;
}

__global__ void softmax_rows_k(float* s, int n, int ld) {
  float* row = s + (long long)blockIdx.y * n * ld + (long long)blockIdx.x * ld;
  __shared__ float red[32];
  __shared__ float bcast;
  int tid = threadIdx.x;
  int nw = blockDim.x >> 5;

  float m = -1e30f;
  for (int j = tid; j < n; j += blockDim.x) m = fmaxf(m, row[j]);
  for (int o = 16; o; o >>= 1) m = fmaxf(m, __shfl_xor_sync(0xffffffffu, m, o));
  if ((tid & 31) == 0) red[tid >> 5] = m;
  __syncthreads();
  if (tid < 32) {
    float v = (tid < nw) ? red[tid] : -1e30f;
    for (int o = 16; o; o >>= 1) v = fmaxf(v, __shfl_xor_sync(0xffffffffu, v, o));
    if (tid == 0) bcast = v;
  }
  __syncthreads();
  m = bcast;

  float sum = 0.f;
  for (int j = tid; j < n; j += blockDim.x) {
    float e = __expf(row[j] - m);
    row[j] = e;
    sum += e;
  }
  for (int o = 16; o; o >>= 1) sum += __shfl_xor_sync(0xffffffffu, sum, o);
  if ((tid & 31) == 0) red[tid >> 5] = sum;
  __syncthreads();
  if (tid < 32) {
    float v = (tid < nw) ? red[tid] : 0.f;
    for (int o = 16; o; o >>= 1) v += __shfl_xor_sync(0xffffffffu, v, o);
    if (tid == 0) bcast = v;
  }
  __syncthreads();
  float inv = 1.f / bcast;
  for (int j = tid; j < n; j += blockDim.x) row[j] *= inv;
}

__global__ void add_ln_k(const float* x, const float* r, const float* g,
                         const float* b, float* out) {
  long long base = (long long)blockIdx.x * D;
  __shared__ float buf[D];
  __shared__ float redA[32], redB[32];
  __shared__ float sh_m, sh_inv;
  int tid = threadIdx.x;
  int nw = blockDim.x >> 5;

  float s = 0.f, s2 = 0.f;
  for (int d = tid; d < D; d += blockDim.x) {
    float v = x[base + d] + r[base + d];
    buf[d] = v;
    s += v;
    s2 += v * v;
  }
  for (int o = 16; o; o >>= 1) {
    s += __shfl_xor_sync(0xffffffffu, s, o);
    s2 += __shfl_xor_sync(0xffffffffu, s2, o);
  }
  if ((tid & 31) == 0) { redA[tid >> 5] = s; redB[tid >> 5] = s2; }
  __syncthreads();
  if (tid < 32) {
    float a2 = (tid < nw) ? redA[tid] : 0.f;
    float b2 = (tid < nw) ? redB[tid] : 0.f;
    for (int o = 16; o; o >>= 1) {
      a2 += __shfl_xor_sync(0xffffffffu, a2, o);
      b2 += __shfl_xor_sync(0xffffffffu, b2, o);
    }
    if (tid == 0) {
      float mean = a2 / D;
      float var = b2 / D - mean * mean;
      sh_m = mean;
      sh_inv = rsqrtf(var + 1e-5f);
    }
  }
  __syncthreads();
  float mean = sh_m, inv = sh_inv;
  for (int d = tid; d < D; d += blockDim.x)
    out[base + d] = (buf[d] - mean) * inv * g[d] + b[d];
}

// ---------------------------------------------------------------------------
// Host-side driver
// ---------------------------------------------------------------------------
static inline int cdiv(int a, int b) { return (a + b - 1) / b; }

struct Wts {
  const float *ew, *eb, *rw, *rb, *ow, *ob, *l1g, *l1b, *w1, *b1, *w2, *b2,
      *l2g, *l2b;
};

static void run_block(float* sc, const float* t, float* out, int layer, int n,
                      const Wts& w) {
  const int M = B * n;
  const int n4 = (n + 3) & ~3;
  float* rout = sc + OFF_ROUT;
  float* qkv = sc + OFF_QKV;
  float* sco = sc + OFF_SC;
  float* y = sc + OFF_Y;
  float* a = sc + OFF_A;
  float* x1 = sc + OFF_X1;
  float* h = sc + OFF_H;

  GemmP p;
  auto reset = [&]() {
    p = GemmP{};
    p.aDiv = p.bDiv = p.cDiv = p.biasDiv = 1;
    p.scale = 1.f;
  };

  // 1. routing logits + softmax over experts (fp32 SIMT, N=20)
  reset();
  p.A = t; p.Bm = w.rw + (long long)layer * D * E;
  p.bias = w.rb + (long long)layer * E; p.C = rout;
  p.M = M; p.N = E; p.K = D; p.lda = D; p.ldb = E; p.ldc = E;
  sgemm2_k<64, 64, 16, 4, 4><<<dim3(1, cdiv(M, 64), 1), 256>>>(p);
  softmaxE_k<<<cdiv(M, 256), 256>>>(rout, M);

  // 2. qkv = t @ expert_w[e] + expert_b[e], split-stored as Q/K/V [z][3][n][52]
  reset();
  p.A = t; p.lda = D; p.aDiv = E; p.as1 = (long long)n * D;
  p.Bm = w.ew + (long long)layer * E * D * TH; p.ldb = TH;
  p.bDiv = E; p.bs2 = (long long)D * TH;
  p.bias = w.eb + (long long)layer * E * TH; p.biasDiv = E; p.biasS = TH;
  p.C = qkv; p.ldc = HD_P; p.cs1 = 3LL * n * HD_P;
  p.splitStride = (long long)n * HD_P;
  p.M = n; p.N = TH; p.K = D;
  tmma_k<128, 64, 32, 32, 0, 4, 0>
      <<<dim3(cdiv(TH, 64), cdiv(n, 128), B * E), 256>>>(p);

  // 3. scores = Q @ K^T * HD^-0.5 (NT), batched over (b,e)
  reset();
  p.A = qkv; p.lda = HD_P; p.as1 = 3LL * n * HD_P;
  p.Bm = qkv + (long long)n * HD_P; p.ldb = HD_P; p.bs1 = 3LL * n * HD_P;
  p.C = sco; p.ldc = n4; p.cs1 = (long long)n * n4;
  p.M = n; p.N = n; p.K = HD;
  p.scale = 0.14142135623730950488f;  // 1/sqrt(50)
  tmma_k<128, 64, 32, 32, 1, 2>
      <<<dim3(cdiv(n, 64), cdiv(n, 128), B * E), 256>>>(p);

  softmax_rows_k<<<dim3(n, B * E), 256>>>(sco, n, n4);

  // 4. y[:, e*HD:(e+1)*HD] = (P @ V) * routing[b, s, e]
  reset();
  p.A = sco; p.lda = n4; p.as1 = (long long)n * n4;
  p.Bm = qkv + 2LL * n * HD_P; p.ldb = HD_P; p.bs1 = 3LL * n * HD_P;
  p.C = y; p.ldc = D; p.cDiv = E; p.cs1 = (long long)n * D; p.cs2 = HD;
  p.M = n; p.N = HD; p.K = n;
  p.rout = rout; p.routN = n;
  tmma_k<128, 64, 32, 32, 0, 3><<<dim3(1, cdiv(n, 128), B * E), 256>>>(p);

  // 5. a = y @ out_w + out_b
  reset();
  p.A = y; p.lda = D;
  p.Bm = w.ow + (long long)layer * D * D; p.ldb = D;
  p.bias = w.ob + (long long)layer * D;
  p.C = a; p.ldc = D;
  p.M = M; p.N = D; p.K = D;
  tmma_k<64, 128, 32, 32, 0, 0>
      <<<dim3(cdiv(D, 128), cdiv(M, 64), 1), 256>>>(p);

  // 6. x1 = LN1(t + a)
  add_ln_k<<<M, 256>>>(t, a, w.l1g + (long long)layer * D,
                       w.l1b + (long long)layer * D, x1);

  // 7. h = gelu(x1 @ ff_w1 + ff_b1)
  reset();
  p.A = x1; p.lda = D;
  p.Bm = w.w1 + (long long)layer * D * F; p.ldb = F;
  p.bias = w.b1 + (long long)layer * F;
  p.C = h; p.ldc = F;
  p.M = M; p.N = F; p.K = D;
  tmma_k<64, 128, 32, 32, 0, 1>
      <<<dim3(cdiv(F, 128), cdiv(M, 64), 1), 256>>>(p);

  // 8. f = h @ ff_w2 + ff_b2 (into y, reuse)
  reset();
  p.A = h; p.lda = F;
  p.Bm = w.w2 + (long long)layer * F * D; p.ldb = D;
  p.bias = w.b2 + (long long)layer * D;
  p.C = y; p.ldc = D;
  p.M = M; p.N = D; p.K = F;
  tmma_k<64, 128, 32, 32, 0, 0>
      <<<dim3(cdiv(D, 128), cdiv(M, 64), 1), 256>>>(p);

  // 9. out = LN2(x1 + f)
  add_ln_k<<<M, 256>>>(x1, y, w.l2g + (long long)layer * D,
                       w.l2b + (long long)layer * D, out);
}

extern "C" void kernel_launch(void* const* d_in, const int* in_sizes, int n_in,
                              void* d_out, int out_size) {
  (void)in_sizes; (void)n_in; (void)out_size;
  float* sc = nullptr;
  cudaGetSymbolAddress((void**)&sc, g_scratch);

  const float* x_in = (const float*)d_in[0];
  Wts w;
  w.ew = (const float*)d_in[1];  w.eb = (const float*)d_in[2];
  w.rw = (const float*)d_in[3];  w.rb = (const float*)d_in[4];
  w.ow = (const float*)d_in[5];  w.ob = (const float*)d_in[6];
  w.l1g = (const float*)d_in[7]; w.l1b = (const float*)d_in[8];
  w.w1 = (const float*)d_in[9];  w.b1 = (const float*)d_in[10];
  w.w2 = (const float*)d_in[11]; w.b2 = (const float*)d_in[12];
  w.l2g = (const float*)d_in[13]; w.l2b = (const float*)d_in[14];

  copy_k<<<cdiv((int)NX, 256), 256>>>(sc + OFF_X, x_in, NX);

  run_block(sc, sc + OFF_X, sc + OFF_X, 0, S, w);

  for (int c = 0; c < CYCLES; c++) {
    zero_k<<<cdiv((int)NX, 256), 256>>>(sc + OFF_XNEW, NX);
    for (int j = 0; j < 4; j++) {
      int nseg = SEG_N[j];
      int tot = B * nseg * D;
      gather_k<<<cdiv(tot, 256), 256>>>(sc + OFF_T, sc + OFF_X, nseg, SEG_ST[j],
                                        SEG_P1[j]);
      run_block(sc, sc + OFF_T, sc + OFF_A, 1 + 4 * c + j, nseg, w);
      scatter_add_k<<<cdiv(tot, 256), 256>>>(sc + OFF_XNEW, sc + OFF_A, nseg,
                                             SEG_ST[j], SEG_P1[j]);
    }
    div_counts_k<<<cdiv((int)NX, 256), 256>>>(sc + OFF_X, sc + OFF_XNEW);
  }

  run_block(sc, sc + OFF_X, (float*)d_out, 13, S, w);
}

// round 7
// speedup vs baseline: 1.9159x; 1.9041x over previous
#include <cuda_runtime.h>
#include <math.h>
#include <stdint.h>

// ---------------------------------------------------------------------------
// SLAMv2: 14-layer MoE-attention transformer, segmented schedule.
// Round 7: TF32 mma.sync GEMM with cp.async 4-stage pipeline, k-slot remap
// (plain k-contiguous smem, LDS.64 fragments, zero staging STS),
// one-time weight repack+tf32-round, producer-side activation rounding.
// ---------------------------------------------------------------------------

namespace {
constexpr int B = 2, S = 1024, D = 1000, E = 20, HD = 50, TH = 3 * HD;
constexpr int HD_P = 52;    // padded head dim
constexpr int TH_P = 160;   // padded qkv width (16B-aligned rows for cp.async)
constexpr int F = 2048, CYCLES = 3, L = 14;

constexpr long long NX = (long long)B * S * D;  // 2,048,000
constexpr long long OFF_X    = 0;
constexpr long long OFF_XNEW = OFF_X + NX;
constexpr long long OFF_T    = OFF_XNEW + NX;
constexpr long long OFF_X1   = OFF_T + NX;
constexpr long long OFF_Y    = OFF_X1 + NX;
constexpr long long OFF_A    = OFF_Y + NX;
constexpr long long OFF_ROUT = OFF_A + NX;                       // B*S*E
constexpr long long OFF_H    = OFF_ROUT + (long long)B * S * E;  // B*S*F
constexpr long long OFF_QKV  = OFF_H + (long long)B * S * F;     // B*E*3*S*HD_P
constexpr long long OFF_SC   = OFF_QKV + (long long)B * E * 3 * S * HD_P;
constexpr long long OFF_EWP  = OFF_SC + (long long)B * E * S * S;
constexpr long long OFF_OWR  = OFF_EWP + (long long)L * E * D * TH_P;
constexpr long long OFF_W1R  = OFF_OWR + (long long)L * D * D;
constexpr long long OFF_W2R  = OFF_W1R + (long long)L * D * F;
constexpr long long TOTAL    = OFF_W2R + (long long)L * F * D;

// Segment schedule for S=1024: (0,460) (256,665) (460,870) (665,1024)+wrap 51
constexpr int SEG_ST[4] = {0, 256, 460, 665};
constexpr int SEG_N[4]  = {460, 409, 410, 410};
constexpr int SEG_P1[4] = {460, 409, 410, 359};
}  // namespace

__device__ float g_scratch[TOTAL];

struct GemmP {
  const float* A; const float* Bm; const float* bias; float* C;
  int M, N, K, lda, ldb, ldc;
  int aDiv; long long as1, as2;
  int bDiv; long long bs1, bs2;
  int cDiv; long long cs1, cs2;
  int biasDiv; long long biasS;
  long long splitStride;
  float scale;
  const float* rout; int routN;
};

__device__ __forceinline__ float to_tf32(float x) {
  asm("cvt.rna.tf32.f32 %0, %0;" : "+f"(x));
  return x;
}

__device__ __forceinline__ void cp16(uint32_t dst, const float* src, int bytes) {
  asm volatile("cp.async.cg.shared.global [%0], [%1], 16, %2;\n"
               :: "r"(dst), "l"(src), "r"(bytes));
}
__device__ __forceinline__ void cp_commit() {
  asm volatile("cp.async.commit_group;\n");
}
template <int N>
__device__ __forceinline__ void cp_wait() {
  asm volatile("cp.async.wait_group %0;\n" :: "n"(N));
}

// ---------------------------------------------------------------------------
// TF32 tensor-core GEMM; cp.async 4-stage ring; k-slot remap fragments.
// BTRANS: 0 -> B is [K,N] (smem Bs[k][n]); 1 -> B is [N,K] (smem Bs[n][k]).
// EPI: 0 +bias; 1 +bias,GELU(round); 2 *scale; 3 *routing(round);
//      4 +bias,split-QKV(round).
// Inputs assumed pre-rounded to tf32 by producers.
// ---------------------------------------------------------------------------
template <int BM, int BN, int WM, int WN, int BTRANS, int EPI>
__global__ __launch_bounds__(256) void tmma_k(GemmP p) {
  constexpr int BK = 16, ST = 4;
  constexpr int SKA = BK + 4;   // 20 floats, 80B rows (16B-aligned)
  constexpr int LDB0 = BN + 4;  // for BTRANS=0 layout
  constexpr int ASZ = BM * SKA;
  constexpr int BSZ = BTRANS ? BN * SKA : BK * LDB0;
  constexpr int NWN = BN / WN;
  constexpr int MT = WM / 16, NT = WN / 8;
  constexpr int AV_ = BM / 64;  // 16B chunks per thread for A
  constexpr int BV_ = BN / 64;  // 16B chunks per thread for B
  static_assert((BM / WM) * (BN / WN) == 8, "need 8 warps");

  extern __shared__ float sm[];
  float* As = sm;              // [ST][BM][SKA]
  float* Bs = sm + ST * ASZ;   // [ST][BSZ]
  const uint32_t a_u32 = (uint32_t)__cvta_generic_to_shared(As);
  const uint32_t b_u32 = (uint32_t)__cvta_generic_to_shared(Bs);

  const int z = blockIdx.z;
  const float* Ab =
      p.A + (long long)(z / p.aDiv) * p.as1 + (long long)(z % p.aDiv) * p.as2;
  const float* Bb =
      p.Bm + (long long)(z / p.bDiv) * p.bs1 + (long long)(z % p.bDiv) * p.bs2;
  float* Cb =
      p.C + (long long)(z / p.cDiv) * p.cs1 + (long long)(z % p.cDiv) * p.cs2;

  const int m0 = blockIdx.y * BM, n0 = blockIdx.x * BN;
  const int tid = threadIdx.x;
  const int warp = tid >> 5, lane = tid & 31;
  const int g = lane >> 2, t = lane & 3;
  const int wm = (warp / NWN) * WM, wn = (warp % NWN) * WN;

  auto issue = [&](int it) {
    const int s = it % ST;
    const int kb = it * BK;
    // A tile: BM x 16, k-contiguous rows
#pragma unroll
    for (int v = 0; v < AV_; v++) {
      int idx = tid + v * 256;
      int m = idx >> 2, c4 = (idx & 3) * 4;
      int gm = m0 + m, gk = kb + c4;
      int by = 0;
      if (gm < p.M) {
        int rem = (p.K - gk) * 4;
        by = rem > 16 ? 16 : (rem > 0 ? rem : 0);
      }
      const float* src = Ab + (long long)(by ? gm : 0) * p.lda + (by ? gk : 0);
      cp16(a_u32 + (uint32_t)(s * ASZ + m * SKA + c4) * 4u, src, by);
    }
    // B tile
    if (BTRANS == 0) {
#pragma unroll
      for (int v = 0; v < BV_; v++) {
        int idx = tid + v * 256;
        int kk = idx / (BN / 4), n4 = (idx % (BN / 4)) * 4;
        int gk = kb + kk, gn = n0 + n4;
        int by = 0;
        if (gk < p.K) {
          int rem = (p.N - gn) * 4;
          by = rem > 16 ? 16 : (rem > 0 ? rem : 0);
        }
        const float* src = Bb + (long long)(by ? gk : 0) * p.ldb + (by ? gn : 0);
        cp16(b_u32 + (uint32_t)(s * BSZ + kk * LDB0 + n4) * 4u, src, by);
      }
    } else {
#pragma unroll
      for (int v = 0; v < BV_; v++) {
        int idx = tid + v * 256;
        int n = idx >> 2, c4 = (idx & 3) * 4;
        int gn = n0 + n, gk = kb + c4;
        int by = 0;
        if (gn < p.N) {
          int rem = (p.K - gk) * 4;
          by = rem > 16 ? 16 : (rem > 0 ? rem : 0);
        }
        const float* src = Bb + (long long)(by ? gn : 0) * p.ldb + (by ? gk : 0);
        cp16(b_u32 + (uint32_t)(s * BSZ + n * SKA + c4) * 4u, src, by);
      }
    }
  };

  float c[MT][NT][4];
#pragma unroll
  for (int i = 0; i < MT; i++)
#pragma unroll
    for (int j = 0; j < NT; j++)
#pragma unroll
      for (int r = 0; r < 4; r++) c[i][j][r] = 0.f;

  // k-slot remap: instruction slot t <- physical k=2t, slot t+4 <- k=2t+1.
  // A-frag (a0,a2) = one LDS.64 at [row][kq*8+2t]; (a1,a3) at row+8.
  // BTRANS=1 B-frag (b0,b1) = one LDS.64. BTRANS=0: two LDS.32.
  auto comp = [&](int s) {
    const float* Asb = As + s * ASZ;
    const float* Bsb = Bs + s * BSZ;
#pragma unroll
    for (int kq = 0; kq < 2; kq++) {
      const int ko = kq * 8 + 2 * t;
      float2 af[MT][2];
#pragma unroll
      for (int mt = 0; mt < MT; mt++) {
        int r0 = wm + mt * 16 + g;
        af[mt][0] = *reinterpret_cast<const float2*>(&Asb[r0 * SKA + ko]);
        af[mt][1] = *reinterpret_cast<const float2*>(&Asb[(r0 + 8) * SKA + ko]);
      }
      float bx[NT], by_[NT];
#pragma unroll
      for (int nt = 0; nt < NT; nt++) {
        int col = wn + nt * 8 + g;
        if (BTRANS == 1) {
          float2 bb = *reinterpret_cast<const float2*>(&Bsb[col * SKA + ko]);
          bx[nt] = bb.x;
          by_[nt] = bb.y;
        } else {
          bx[nt] = Bsb[ko * LDB0 + col];
          by_[nt] = Bsb[(ko + 1) * LDB0 + col];
        }
      }
#pragma unroll
      for (int mt = 0; mt < MT; mt++)
#pragma unroll
        for (int nt = 0; nt < NT; nt++) {
          asm volatile(
              "mma.sync.aligned.m16n8k8.row.col.f32.tf32.tf32.f32 "
              "{%0,%1,%2,%3}, {%4,%5,%6,%7}, {%8,%9}, {%0,%1,%2,%3};"
              : "+f"(c[mt][nt][0]), "+f"(c[mt][nt][1]), "+f"(c[mt][nt][2]),
                "+f"(c[mt][nt][3])
              : "r"(__float_as_uint(af[mt][0].x)),
                "r"(__float_as_uint(af[mt][1].x)),
                "r"(__float_as_uint(af[mt][0].y)),
                "r"(__float_as_uint(af[mt][1].y)),
                "r"(__float_as_uint(bx[nt])), "r"(__float_as_uint(by_[nt])));
        }
    }
  };

  const int iters = (p.K + BK - 1) / BK;
#pragma unroll
  for (int s = 0; s < ST - 1; s++) {
    if (s < iters) issue(s);
    cp_commit();
  }
  for (int it = 0; it < iters; it++) {
    cp_wait<ST - 2>();
    __syncthreads();
    if (it + ST - 1 < iters) issue(it + ST - 1);
    cp_commit();
    comp(it % ST);
  }

  const float* biasb = nullptr;
  if ((EPI == 0 || EPI == 1 || EPI == 4) && p.bias)
    biasb = p.bias + (long long)(z % p.biasDiv) * p.biasS;

#pragma unroll
  for (int mt = 0; mt < MT; mt++)
#pragma unroll
    for (int nt = 0; nt < NT; nt++)
#pragma unroll
      for (int r = 0; r < 4; r++) {
        int row = m0 + wm + mt * 16 + g + ((r >> 1) ? 8 : 0);
        int col = n0 + wn + nt * 8 + 2 * t + (r & 1);
        if (row >= p.M || col >= p.N) continue;
        float v = c[mt][nt][r];
        if (biasb) v += biasb[col];
        if (EPI == 1) {
          v = 0.5f * v * (1.f + erff(v * 0.70710678118654752f));
          v = to_tf32(v);
        }
        if (EPI == 2) v *= p.scale;
        if (EPI == 3) {
          v *= p.rout[((long long)(z / p.cDiv) * p.routN + row) * E +
                      (z % p.cDiv)];
          v = to_tf32(v);
        }
        if (EPI == 4) {
          v = to_tf32(v);
          int h = col / HD, s2 = col - h * HD;
          Cb[(long long)h * p.splitStride + (long long)row * p.ldc + s2] = v;
        } else {
          Cb[(long long)row * p.ldc + col] = v;
        }
      }
}

// ---------------------------------------------------------------------------
// SIMT SGEMM (tiny routing GEMM, N=20)
// ---------------------------------------------------------------------------
template <int BM, int BN, int BK, int TM, int TN>
__global__ __launch_bounds__((BM / TM) * (BN / TN)) void sgemm2_k(GemmP p) {
  constexpr int NTHR = (BM / TM) * (BN / TN);
  constexpr int TX = BN / TN;
  __shared__ float As[BK][BM + 4];
  __shared__ float Bs[BK][BN + 4];

  const float* Ab = p.A;
  const float* Bb = p.Bm;
  float* Cb = p.C;

  const int m0 = blockIdx.y * BM, n0 = blockIdx.x * BN;
  const int tid = threadIdx.x;
  const int tx = tid % TX, ty = tid / TX;

  float acc[TM][TN];
#pragma unroll
  for (int i = 0; i < TM; i++)
#pragma unroll
    for (int j = 0; j < TN; j++) acc[i][j] = 0.f;

  for (int k0 = 0; k0 < p.K; k0 += BK) {
    for (int idx = tid; idx < BM * BK; idx += NTHR) {
      int m = idx / BK, kk = idx % BK;
      int gm = m0 + m, gk = k0 + kk;
      As[kk][m] = (gm < p.M && gk < p.K) ? Ab[(long long)gm * p.lda + gk] : 0.f;
    }
    for (int idx = tid; idx < BK * BN; idx += NTHR) {
      int kk = idx / BN, nn = idx % BN;
      int gk = k0 + kk, gn = n0 + nn;
      Bs[kk][nn] = (gk < p.K && gn < p.N) ? Bb[(long long)gk * p.ldb + gn] : 0.f;
    }
    __syncthreads();
#pragma unroll
    for (int kk = 0; kk < BK; kk++) {
      float a[TM], b[TN];
#pragma unroll
      for (int i = 0; i < TM; i++) a[i] = As[kk][ty * TM + i];
#pragma unroll
      for (int j = 0; j < TN; j++) b[j] = Bs[kk][tx * TN + j];
#pragma unroll
      for (int i = 0; i < TM; i++)
#pragma unroll
        for (int j = 0; j < TN; j++) acc[i][j] += a[i] * b[j];
    }
    __syncthreads();
  }

#pragma unroll
  for (int i = 0; i < TM; i++) {
    int row = m0 + ty * TM + i;
    if (row >= p.M) continue;
#pragma unroll
    for (int j = 0; j < TN; j++) {
      int col = n0 + tx * TN + j;
      if (col >= p.N) continue;
      float v = acc[i][j] + (p.bias ? p.bias[col] : 0.f);
      Cb[(long long)row * p.ldc + col] = v;
    }
  }
}

// ---------------------------------------------------------------------------
// Small kernels
// ---------------------------------------------------------------------------
__global__ void copy_round_k(float* dst, const float* src, long long n) {
  long long i = (long long)blockIdx.x * blockDim.x + threadIdx.x;
  if (i < n) dst[i] = to_tf32(src[i]);
}

__global__ void zero_k(float* dst, long long n) {
  long long i = (long long)blockIdx.x * blockDim.x + threadIdx.x;
  if (i < n) dst[i] = 0.f;
}

// expert_w [L,E,D,150] -> padded+rounded [L,E,D,160]
__global__ void repack_ew_k(float* dst, const float* src) {
  long long i = (long long)blockIdx.x * blockDim.x + threadIdx.x;
  long long tot = (long long)L * E * D * TH_P;
  if (i >= tot) return;
  int col = (int)(i % TH_P);
  long long base = i / TH_P;
  dst[i] = (col < TH) ? to_tf32(src[base * TH + col]) : 0.f;
}

__global__ void gather_k(float* dst, const float* src, int nseg, int st, int p1) {
  long long i = (long long)blockIdx.x * blockDim.x + threadIdx.x;
  long long tot = (long long)B * nseg * D;
  if (i >= tot) return;
  int d = (int)(i % D);
  long long r = i / D;
  int ii = (int)(r % nseg);
  int b_ = (int)(r / nseg);
  int si = (ii < p1) ? (st + ii) : (ii - p1);
  dst[i] = src[((long long)b_ * S + si) * D + d];
}

__global__ void scatter_add_k(float* dst, const float* src, int nseg, int st,
                              int p1) {
  long long i = (long long)blockIdx.x * blockDim.x + threadIdx.x;
  long long tot = (long long)B * nseg * D;
  if (i >= tot) return;
  int d = (int)(i % D);
  long long r = i / D;
  int ii = (int)(r % nseg);
  int b_ = (int)(r / nseg);
  int si = (ii < p1) ? (st + ii) : (ii - p1);
  dst[((long long)b_ * S + si) * D + d] += src[i];
}

__device__ __forceinline__ float seg_cnt(int i) {
  float c = 0.f;
  c += (i < 460);
  c += (i >= 256 && i < 665);
  c += (i >= 460 && i < 870);
  c += (i >= 665);
  c += (i < 51);
  return c;
}

__global__ void div_counts_k(float* x, const float* xn) {
  long long i = (long long)blockIdx.x * blockDim.x + threadIdx.x;
  if (i >= NX) return;
  int ii = (int)((i / D) % S);
  x[i] = to_tf32(xn[i] / seg_cnt(ii));
}

__global__ void softmaxE_k(float* r, int rows) {
  int i = blockIdx.x * blockDim.x + threadIdx.x;
  if (i >= rows) return;
  float* p = r + (long long)i * E;
  float m = -1e30f;
  for (int e = 0; e < E; e++) m = fmaxf(m, p[e]);
  float s = 0.f;
  for (int e = 0; e < E; e++) {
    float v = __expf(p[e] - m);
    p[e] = v;
    s += v;
  }
  float inv = 1.f / s;
  for (int e = 0; e < E; e++) p[e] *= inv;
}

// In-place row softmax (output rounded to tf32 — feeds AV GEMM).
__global__ void softmax_rows_k(float* s, int n, int ld) {
  float* row = s + (long long)blockIdx.y * n * ld + (long long)blockIdx.x * ld;
  __shared__ float red[32];
  __shared__ float bcast;
  int tid = threadIdx.x;
  int nw = blockDim.x >> 5;

  float m = -1e30f;
  for (int j = tid; j < n; j += blockDim.x) m = fmaxf(m, row[j]);
  for (int o = 16; o; o >>= 1) m = fmaxf(m, __shfl_xor_sync(0xffffffffu, m, o));
  if ((tid & 31) == 0) red[tid >> 5] = m;
  __syncthreads();
  if (tid < 32) {
    float v = (tid < nw) ? red[tid] : -1e30f;
    for (int o = 16; o; o >>= 1) v = fmaxf(v, __shfl_xor_sync(0xffffffffu, v, o));
    if (tid == 0) bcast = v;
  }
  __syncthreads();
  m = bcast;

  float sum = 0.f;
  for (int j = tid; j < n; j += blockDim.x) {
    float e = __expf(row[j] - m);
    row[j] = e;
    sum += e;
  }
  for (int o = 16; o; o >>= 1) sum += __shfl_xor_sync(0xffffffffu, sum, o);
  if ((tid & 31) == 0) red[tid >> 5] = sum;
  __syncthreads();
  if (tid < 32) {
    float v = (tid < nw) ? red[tid] : 0.f;
    for (int o = 16; o; o >>= 1) v += __shfl_xor_sync(0xffffffffu, v, o);
    if (tid == 0) bcast = v;
  }
  __syncthreads();
  float inv = 1.f / bcast;
  for (int j = tid; j < n; j += blockDim.x) row[j] = to_tf32(row[j] * inv);
}

// out = layernorm(x + r) * g + b; CVT: round output to tf32 (GEMM input).
template <bool CVT>
__global__ void add_ln_k(const float* x, const float* r, const float* g,
                         const float* b, float* out) {
  long long base = (long long)blockIdx.x * D;
  __shared__ float buf[D];
  __shared__ float redA[32], redB[32];
  __shared__ float sh_m, sh_inv;
  int tid = threadIdx.x;
  int nw = blockDim.x >> 5;

  float s = 0.f, s2 = 0.f;
  for (int d = tid; d < D; d += blockDim.x) {
    float v = x[base + d] + r[base + d];
    buf[d] = v;
    s += v;
    s2 += v * v;
  }
  for (int o = 16; o; o >>= 1) {
    s += __shfl_xor_sync(0xffffffffu, s, o);
    s2 += __shfl_xor_sync(0xffffffffu, s2, o);
  }
  if ((tid & 31) == 0) { redA[tid >> 5] = s; redB[tid >> 5] = s2; }
  __syncthreads();
  if (tid < 32) {
    float a2 = (tid < nw) ? redA[tid] : 0.f;
    float b2 = (tid < nw) ? redB[tid] : 0.f;
    for (int o = 16; o; o >>= 1) {
      a2 += __shfl_xor_sync(0xffffffffu, a2, o);
      b2 += __shfl_xor_sync(0xffffffffu, b2, o);
    }
    if (tid == 0) {
      float mean = a2 / D;
      float var = b2 / D - mean * mean;
      sh_m = mean;
      sh_inv = rsqrtf(var + 1e-5f);
    }
  }
  __syncthreads();
  float mean = sh_m, inv = sh_inv;
  for (int d = tid; d < D; d += blockDim.x) {
    float v = (buf[d] - mean) * inv * g[d] + b[d];
    out[base + d] = CVT ? to_tf32(v) : v;
  }
}

// ---------------------------------------------------------------------------
// Host-side driver
// ---------------------------------------------------------------------------
static inline int cdiv(int a, int b) { return (a + b - 1) / b; }

struct Wts {
  const float *ew, *eb, *rw, *rb, *ow, *ob, *l1g, *l1b, *w1, *b1, *w2, *b2,
      *l2g, *l2b;
};

// dynamic smem sizes per instantiation (ST=4, SKA=20)
constexpr int SMEM_128x64_T0 = 4 * (128 * 20 + 16 * 68) * 4;    // 58368
constexpr int SMEM_128x128_T1 = 4 * (128 * 20 + 128 * 20) * 4;  // 81920
constexpr int SMEM_64x128_T0 = 4 * (64 * 20 + 16 * 132) * 4;    // 54272

static void run_block(float* sc, const float* t, float* out, int layer, int n,
                      const Wts& w) {
  const int M = B * n;
  const int n4 = (n + 3) & ~3;
  float* rout = sc + OFF_ROUT;
  float* qkv = sc + OFF_QKV;
  float* sco = sc + OFF_SC;
  float* y = sc + OFF_Y;
  float* a = sc + OFF_A;
  float* x1 = sc + OFF_X1;
  float* h = sc + OFF_H;
  const float* ewp = sc + OFF_EWP + (long long)layer * E * D * TH_P;
  const float* owr = sc + OFF_OWR + (long long)layer * D * D;
  const float* w1r = sc + OFF_W1R + (long long)layer * D * F;
  const float* w2r = sc + OFF_W2R + (long long)layer * F * D;

  GemmP p;
  auto reset = [&]() {
    p = GemmP{};
    p.aDiv = p.bDiv = p.cDiv = p.biasDiv = 1;
    p.scale = 1.f;
  };

  // 1. routing logits + softmax over experts (fp32 SIMT, N=20)
  reset();
  p.A = t; p.Bm = w.rw + (long long)layer * D * E;
  p.bias = w.rb + (long long)layer * E; p.C = rout;
  p.M = M; p.N = E; p.K = D; p.lda = D; p.ldb = E; p.ldc = E;
  sgemm2_k<64, 64, 16, 4, 4><<<dim3(1, cdiv(M, 64), 1), 256>>>(p);
  softmaxE_k<<<cdiv(M, 256), 256>>>(rout, M);

  // 2. qkv = t @ ewp[e] + eb[e], split-stored as Q/K/V [z][3][n][52]
  reset();
  p.A = t; p.lda = D; p.aDiv = E; p.as1 = (long long)n * D;
  p.Bm = ewp; p.ldb = TH_P;
  p.bDiv = E; p.bs2 = (long long)D * TH_P;
  p.bias = w.eb + (long long)layer * E * TH; p.biasDiv = E; p.biasS = TH;
  p.C = qkv; p.ldc = HD_P; p.cs1 = 3LL * n * HD_P;
  p.splitStride = (long long)n * HD_P;
  p.M = n; p.N = TH; p.K = D;
  tmma_k<128, 64, 32, 32, 0, 4>
      <<<dim3(3, cdiv(n, 128), B * E), 256, SMEM_128x64_T0>>>(p);

  // 3. scores = Q @ K^T * HD^-0.5 (NT), batched over (b,e)
  reset();
  p.A = qkv; p.lda = HD_P; p.as1 = 3LL * n * HD_P;
  p.Bm = qkv + (long long)n * HD_P; p.ldb = HD_P; p.bs1 = 3LL * n * HD_P;
  p.C = sco; p.ldc = n4; p.cs1 = (long long)n * n4;
  p.M = n; p.N = n; p.K = HD;
  p.scale = 0.14142135623730950488f;  // 1/sqrt(50)
  tmma_k<128, 128, 64, 32, 1, 2>
      <<<dim3(cdiv(n, 128), cdiv(n, 128), B * E), 256, SMEM_128x128_T1>>>(p);

  softmax_rows_k<<<dim3(n, B * E), 256>>>(sco, n, n4);

  // 4. y[:, e*HD:(e+1)*HD] = (P @ V) * routing[b, s, e]
  reset();
  p.A = sco; p.lda = n4; p.as1 = (long long)n * n4;
  p.Bm = qkv + 2LL * n * HD_P; p.ldb = HD_P; p.bs1 = 3LL * n * HD_P;
  p.C = y; p.ldc = D; p.cDiv = E; p.cs1 = (long long)n * D; p.cs2 = HD;
  p.M = n; p.N = HD; p.K = n;
  p.rout = rout; p.routN = n;
  tmma_k<128, 64, 32, 32, 0, 3>
      <<<dim3(1, cdiv(n, 128), B * E), 256, SMEM_128x64_T0>>>(p);

  // 5. a = y @ out_w + out_b
  reset();
  p.A = y; p.lda = D;
  p.Bm = owr; p.ldb = D;
  p.bias = w.ob + (long long)layer * D;
  p.C = a; p.ldc = D;
  p.M = M; p.N = D; p.K = D;
  tmma_k<64, 128, 32, 32, 0, 0>
      <<<dim3(cdiv(D, 128), cdiv(M, 64), 1), 256, SMEM_64x128_T0>>>(p);

  // 6. x1 = LN1(t + a)
  add_ln_k<true><<<M, 256>>>(t, a, w.l1g + (long long)layer * D,
                             w.l1b + (long long)layer * D, x1);

  // 7. h = gelu(x1 @ ff_w1 + ff_b1)
  reset();
  p.A = x1; p.lda = D;
  p.Bm = w1r; p.ldb = F;
  p.bias = w.b1 + (long long)layer * F;
  p.C = h; p.ldc = F;
  p.M = M; p.N = F; p.K = D;
  tmma_k<64, 128, 32, 32, 0, 1>
      <<<dim3(cdiv(F, 128), cdiv(M, 64), 1), 256, SMEM_64x128_T0>>>(p);

  // 8. f = h @ ff_w2 + ff_b2 (into y, reuse)
  reset();
  p.A = h; p.lda = F;
  p.Bm = w2r; p.ldb = D;
  p.bias = w.b2 + (long long)layer * D;
  p.C = y; p.ldc = D;
  p.M = M; p.N = D; p.K = F;
  tmma_k<64, 128, 32, 32, 0, 0>
      <<<dim3(cdiv(D, 128), cdiv(M, 64), 1), 256, SMEM_64x128_T0>>>(p);

  // 9. out = LN2(x1 + f); final layer's output must stay unrounded
  if (layer == L - 1)
    add_ln_k<false><<<M, 256>>>(x1, y, w.l2g + (long long)layer * D,
                                w.l2b + (long long)layer * D, out);
  else
    add_ln_k<true><<<M, 256>>>(x1, y, w.l2g + (long long)layer * D,
                               w.l2b + (long long)layer * D, out);
}

extern "C" void kernel_launch(void* const* d_in, const int* in_sizes, int n_in,
                              void* d_out, int out_size) {
  (void)in_sizes; (void)n_in; (void)out_size;
  float* sc = nullptr;
  cudaGetSymbolAddress((void**)&sc, g_scratch);

  // raise dynamic smem limits (host-side, not captured; idempotent)
  cudaFuncSetAttribute((const void*)tmma_k<128, 64, 32, 32, 0, 4>,
                       cudaFuncAttributeMaxDynamicSharedMemorySize,
                       SMEM_128x64_T0);
  cudaFuncSetAttribute((const void*)tmma_k<128, 64, 32, 32, 0, 3>,
                       cudaFuncAttributeMaxDynamicSharedMemorySize,
                       SMEM_128x64_T0);
  cudaFuncSetAttribute((const void*)tmma_k<128, 128, 64, 32, 1, 2>,
                       cudaFuncAttributeMaxDynamicSharedMemorySize,
                       SMEM_128x128_T1);
  cudaFuncSetAttribute((const void*)tmma_k<64, 128, 32, 32, 0, 0>,
                       cudaFuncAttributeMaxDynamicSharedMemorySize,
                       SMEM_64x128_T0);
  cudaFuncSetAttribute((const void*)tmma_k<64, 128, 32, 32, 0, 1>,
                       cudaFuncAttributeMaxDynamicSharedMemorySize,
                       SMEM_64x128_T0);

  const float* x_in = (const float*)d_in[0];
  Wts w;
  w.ew = (const float*)d_in[1];  w.eb = (const float*)d_in[2];
  w.rw = (const float*)d_in[3];  w.rb = (const float*)d_in[4];
  w.ow = (const float*)d_in[5];  w.ob = (const float*)d_in[6];
  w.l1g = (const float*)d_in[7]; w.l1b = (const float*)d_in[8];
  w.w1 = (const float*)d_in[9];  w.b1 = (const float*)d_in[10];
  w.w2 = (const float*)d_in[11]; w.b2 = (const float*)d_in[12];
  w.l2g = (const float*)d_in[13]; w.l2b = (const float*)d_in[14];

  // One-time weight repack + tf32 rounding (inside graph; deterministic)
  {
    long long n_ewp = (long long)L * E * D * TH_P;
    repack_ew_k<<<(int)cdiv((int)n_ewp, 256), 256>>>(sc + OFF_EWP, w.ew);
    long long n_ow = (long long)L * D * D;
    copy_round_k<<<(int)cdiv((int)n_ow, 256), 256>>>(sc + OFF_OWR, w.ow, n_ow);
    long long n_w1 = (long long)L * D * F;
    copy_round_k<<<(int)cdiv((int)n_w1, 256), 256>>>(sc + OFF_W1R, w.w1, n_w1);
    long long n_w2 = (long long)L * F * D;
    copy_round_k<<<(int)cdiv((int)n_w2, 256), 256>>>(sc + OFF_W2R, w.w2, n_w2);
  }

  // x = round(input)
  copy_round_k<<<cdiv((int)NX, 256), 256>>>(sc + OFF_X, x_in, NX);

  run_block(sc, sc + OFF_X, sc + OFF_X, 0, S, w);

  for (int c = 0; c < CYCLES; c++) {
    zero_k<<<cdiv((int)NX, 256), 256>>>(sc + OFF_XNEW, NX);
    for (int j = 0; j < 4; j++) {
      int nseg = SEG_N[j];
      int tot = B * nseg * D;
      gather_k<<<cdiv(tot, 256), 256>>>(sc + OFF_T, sc + OFF_X, nseg, SEG_ST[j],
                                        SEG_P1[j]);
      run_block(sc, sc + OFF_T, sc + OFF_A, 1 + 4 * c + j, nseg, w);
      scatter_add_k<<<cdiv(tot, 256), 256>>>(sc + OFF_XNEW, sc + OFF_A, nseg,
                                             SEG_ST[j], SEG_P1[j]);
    }
    div_counts_k<<<cdiv((int)NX, 256), 256>>>(sc + OFF_X, sc + OFF_XNEW);
  }

  run_block(sc, sc + OFF_X, (float*)d_out, 13, S, w);
}